// round 2
// baseline (speedup 1.0000x reference)
#include <cuda_runtime.h>
#include <cuda_bf16.h>

// Scratch accumulators (device globals — no allocation allowed).
// Zero-initialized at module load; finalize kernel resets them after each
// replay so every graph replay starts from zero.
__device__ double g_trans_acc;
__device__ double g_rot_acc;

__device__ __forceinline__ float wrap_angle(float x) {
    // Matches reference: single +/- 2*pi correction, fp32 pi.
    const float PI     = 3.14159265358979323846f;  // rounds to fp32(np.pi)
    const float TWO_PI = 6.28318530717958647692f;
    x = (x >  PI) ? x - TWO_PI : x;
    x = (x < -PI) ? x + TWO_PI : x;
    return x;
}

__device__ __forceinline__ float4 ldcs4(const float4* p) {
    return __ldcs(p);  // streaming load: evict-first, no L2 pollution
}

// Each "unit" = 2 rows of 6 channels = 12 floats = 3 float4 per tensor.
// Lane->channel pattern (channel = idx % 6, rot = channel >= 3):
//   vec0: ch 0,1,2,3  -> T T T R
//   vec1: ch 4,5,0,1  -> R R T T
//   vec2: ch 2,3,4,5  -> T R R R
__global__ void __launch_bounds__(256)
wmse_reduce_kernel(const float4* __restrict__ pred,
                   const float4* __restrict__ targ,
                   long long nunits,
                   const float* __restrict__ pred_s,
                   const float* __restrict__ targ_s,
                   long long tail_begin,
                   long long n_total) {
    float ts = 0.0f, rs = 0.0f;

    const long long stride = (long long)gridDim.x * blockDim.x;
    for (long long u = (long long)blockIdx.x * blockDim.x + threadIdx.x;
         u < nunits; u += stride) {
        const long long b = u * 3;
        float4 p0 = ldcs4(pred + b + 0);
        float4 p1 = ldcs4(pred + b + 1);
        float4 p2 = ldcs4(pred + b + 2);
        float4 q0 = ldcs4(targ + b + 0);
        float4 q1 = ldcs4(targ + b + 1);
        float4 q2 = ldcs4(targ + b + 2);
        float d;
        // vec0: T T T R
        d = p0.x - q0.x;                         ts = fmaf(d, d, ts);
        d = p0.y - q0.y;                         ts = fmaf(d, d, ts);
        d = p0.z - q0.z;                         ts = fmaf(d, d, ts);
        d = wrap_angle(p0.w) - wrap_angle(q0.w); rs = fmaf(d, d, rs);
        // vec1: R R T T
        d = wrap_angle(p1.x) - wrap_angle(q1.x); rs = fmaf(d, d, rs);
        d = wrap_angle(p1.y) - wrap_angle(q1.y); rs = fmaf(d, d, rs);
        d = p1.z - q1.z;                         ts = fmaf(d, d, ts);
        d = p1.w - q1.w;                         ts = fmaf(d, d, ts);
        // vec2: T R R R
        d = p2.x - q2.x;                         ts = fmaf(d, d, ts);
        d = wrap_angle(p2.y) - wrap_angle(q2.y); rs = fmaf(d, d, rs);
        d = wrap_angle(p2.z) - wrap_angle(q2.z); rs = fmaf(d, d, rs);
        d = wrap_angle(p2.w) - wrap_angle(q2.w); rs = fmaf(d, d, rs);
    }

    // Scalar tail (in case total element count isn't a multiple of 12).
    for (long long i = tail_begin + (long long)blockIdx.x * blockDim.x + threadIdx.x;
         i < n_total; i += stride) {
        int c = (int)(i % 6);
        float p = pred_s[i], q = targ_s[i];
        if (c >= 3) {
            float d = wrap_angle(p) - wrap_angle(q);
            rs = fmaf(d, d, rs);
        } else {
            float d = p - q;
            ts = fmaf(d, d, ts);
        }
    }

    // Warp reduce.
    #pragma unroll
    for (int o = 16; o > 0; o >>= 1) {
        ts += __shfl_down_sync(0xffffffffu, ts, o);
        rs += __shfl_down_sync(0xffffffffu, rs, o);
    }

    // Block reduce (8 warps @ 256 threads).
    __shared__ float sT[8];
    __shared__ float sR[8];
    const int wid = threadIdx.x >> 5;
    const int lid = threadIdx.x & 31;
    if (lid == 0) { sT[wid] = ts; sR[wid] = rs; }
    __syncthreads();
    if (wid == 0) {
        ts = (lid < 8) ? sT[lid] : 0.0f;
        rs = (lid < 8) ? sR[lid] : 0.0f;
        #pragma unroll
        for (int o = 4; o > 0; o >>= 1) {
            ts += __shfl_down_sync(0xffffffffu, ts, o);
            rs += __shfl_down_sync(0xffffffffu, rs, o);
        }
        if (lid == 0) {
            atomicAdd(&g_trans_acc, (double)ts);
            atomicAdd(&g_rot_acc,   (double)rs);
        }
    }
}

__global__ void wmse_finalize_kernel(float* __restrict__ out, double inv_count) {
    // inv_count = 1 / (B*T*3): each loss is a mean over half the elements.
    double t = g_trans_acc * inv_count * 1.0;    // TRANS_WEIGHT
    double r = g_rot_acc   * inv_count * 100.0;  // ROT_WEIGHT
    out[0] = (float)(t + r);  // total_loss
    out[1] = (float)t;        // trans_loss
    out[2] = (float)r;        // rot_loss
    // Reset for the next graph replay (globals start zeroed at module load,
    // so the first invocation is also correct).
    g_trans_acc = 0.0;
    g_rot_acc   = 0.0;
}

extern "C" void kernel_launch(void* const* d_in, const int* in_sizes, int n_in,
                              void* d_out, int out_size) {
    const float* pred = (const float*)d_in[0];
    const float* targ = (const float*)d_in[1];
    float* out = (float*)d_out;

    const long long n = (long long)in_sizes[0];   // B*T*6 total elements
    const long long nunits = n / 12;              // 2 rows per unit
    const long long tail_begin = nunits * 12;
    const double inv_count = 1.0 / (double)(n / 2);

    const int threads = 256;
    int blocks = 1184;  // 8 CTAs per SM on 148 SMs; grid-stride covers the rest
    long long max_useful = (nunits + threads - 1) / threads;
    if (max_useful < 1) max_useful = 1;
    if ((long long)blocks > max_useful) blocks = (int)max_useful;

    wmse_reduce_kernel<<<blocks, threads>>>(
        (const float4*)pred, (const float4*)targ, nunits,
        pred, targ, tail_begin, n);
    wmse_finalize_kernel<<<1, 1>>>(out, inv_count);
}